// round 15
// baseline (speedup 1.0000x reference)
#include <cuda_runtime.h>
#include <cuda_bf16.h>
#include <stdint.h>

#define HEADS 16
#define MDIM 4096
#define NDIM 4096
#define KDIM 64
#define QBLK 32

// Quantized (dequantized-to-bf16, exact) operands. rhs stored transposed: [h][n][k].
static __device__ __nv_bfloat16 g_lhs[(size_t)HEADS * MDIM * KDIM];
static __device__ __nv_bfloat16 g_rhs[(size_t)HEADS * NDIM * KDIM];

// ===========================================================================
// Quant phase. Half-block (16 k's) per thread; adjacent threads pair up for
// the full 32-element shared-exponent max via shfl_xor(1). All arithmetic
// exact in fp32 (power-of-two scaling); results <=8 significant bits -> bf16
// exact.
// ===========================================================================
__device__ __forceinline__ void quant_half16(float v[16]) {
    float ma = 0.f;
#pragma unroll
    for (int i = 0; i < 16; i++) ma = fmaxf(ma, fabsf(v[i]));
    ma = fmaxf(ma, __shfl_xor_sync(0xFFFFFFFFu, ma, 1));  // full 32-block max
    if (ma > 0.f) {
        int e = ilogbf(fmaxf(ma, 1e-38f));       // floor(log2(.)) exactly
        float scale = exp2f((float)(7 - e));     // exact power of two
        float step  = exp2f((float)(e - 7));
#pragma unroll
        for (int i = 0; i < 16; i++) {
            float q = rintf(v[i] * scale);       // round-half-even
            q = fminf(fmaxf(q, -128.f), 127.f);
            v[i] = q * step;                     // exact
        }
    } else {
#pragma unroll
        for (int i = 0; i < 16; i++) v[i] = 0.f;
    }
}

__device__ __forceinline__ void pack_store16(__nv_bfloat16* dst, const float v[16]) {
    uint32_t pk[8];
#pragma unroll
    for (int j = 0; j < 8; j++) {
        __nv_bfloat162 h2 = __floats2bfloat162_rn(v[2 * j], v[2 * j + 1]);
        pk[j] = *reinterpret_cast<uint32_t*>(&h2);
    }
    uint4* d4 = reinterpret_cast<uint4*>(dst);
    d4[0] = make_uint4(pk[0], pk[1], pk[2], pk[3]);
    d4[1] = make_uint4(pk[4], pk[5], pk[6], pk[7]);
}

// lhs: 262144 threads (2 per 32-block), float4 loads. 1024 blocks.
// rhs: 65536 threads; each owns 4 adjacent n-columns x 16 k's via float4
//      loads (4x ILP vs scalar). 256 blocks. Fused: 1280 blocks total.
#define QL_BLOCKS 1024
#define QR_BLOCKS 256

__global__ void __launch_bounds__(256) quant_all_kernel(
    const float* __restrict__ lhs, const float* __restrict__ rhs) {
    if (blockIdx.x < QL_BLOCKS) {
        size_t t = blockIdx.x * (size_t)blockDim.x + threadIdx.x;
        const float4* src = reinterpret_cast<const float4*>(lhs + t * 16);
        float v[16];
#pragma unroll
        for (int j = 0; j < 4; j++) {
            float4 f = __ldg(src + j);
            v[4 * j] = f.x; v[4 * j + 1] = f.y; v[4 * j + 2] = f.z; v[4 * j + 3] = f.w;
        }
        quant_half16(v);
        pack_store16(g_lhs + t * 16, v);
    } else {
        // rhs [h][k=64][n]: thread owns columns 4*c4..4*c4+3, k-range
        // [kb*32 + half*16, +16). half = t&1 so the 32-k block max pairs via
        // shfl_xor(1). Loads: float4 per k (16 total), fully coalesced.
        int t    = (blockIdx.x - QL_BLOCKS) * blockDim.x + threadIdx.x;
        int half = t & 1;
        int c4   = (t >> 1) & 1023;
        int kb   = (t >> 11) & 1;
        int h    = t >> 12;
        const float* src = rhs + ((size_t)h * KDIM + kb * QBLK + half * 16) * NDIM + c4 * 4;
        float v[4][16];                 // [col][k]
#pragma unroll
        for (int k = 0; k < 16; k++) {
            float4 f = __ldg(reinterpret_cast<const float4*>(src + (size_t)k * NDIM));
            v[0][k] = f.x; v[1][k] = f.y; v[2][k] = f.z; v[3][k] = f.w;
        }
        // per-column 32-k block max (local 16 + partner's 16)
        float ma[4];
#pragma unroll
        for (int j = 0; j < 4; j++) {
            float m = 0.f;
#pragma unroll
            for (int k = 0; k < 16; k++) m = fmaxf(m, fabsf(v[j][k]));
            ma[j] = m;
        }
#pragma unroll
        for (int j = 0; j < 4; j++)
            ma[j] = fmaxf(ma[j], __shfl_xor_sync(0xFFFFFFFFu, ma[j], 1));
#pragma unroll
        for (int j = 0; j < 4; j++) {
            if (ma[j] > 0.f) {
                int e = ilogbf(fmaxf(ma[j], 1e-38f));
                float scale = exp2f((float)(7 - e));
                float step  = exp2f((float)(e - 7));
#pragma unroll
                for (int k = 0; k < 16; k++) {
                    float q = rintf(v[j][k] * scale);
                    q = fminf(fmaxf(q, -128.f), 127.f);
                    v[j][k] = q * step;
                }
            } else {
#pragma unroll
                for (int k = 0; k < 16; k++) v[j][k] = 0.f;
            }
            // store 16 bf16 (32B) into row (c4*4+j), offset kb*32 + half*16
            uint32_t pk[8];
#pragma unroll
            for (int p = 0; p < 8; p++) {
                __nv_bfloat162 h2 = __floats2bfloat162_rn(v[j][2 * p], v[j][2 * p + 1]);
                pk[p] = *reinterpret_cast<uint32_t*>(&h2);
            }
            uint4* d4 = reinterpret_cast<uint4*>(
                g_rhs + (((size_t)h * NDIM + c4 * 4 + j) * KDIM + kb * QBLK + half * 16));
            d4[0] = make_uint4(pk[0], pk[1], pk[2], pk[3]);
            d4[1] = make_uint4(pk[4], pk[5], pk[6], pk[7]);
        }
    }
}

// ===========================================================================
// GEMM (R14 = best profiled): CTA tile 128x128, K=64 resident, 8 warps =
// 2(m) x 4(n), warp 64x32, cp.async staging, XOR-swizzled rows, 2 CTAs/SM,
// pipelined B-fragment ldmatrix, __stwt (write-through) epilogue.
// ===========================================================================
__global__ void __launch_bounds__(256, 2) bfp_gemm_kernel(float* __restrict__ out) {
    __shared__ __align__(128) char smem[32768];   // A: 16KB, B: 16KB
    const uint32_t sbase = (uint32_t)__cvta_generic_to_shared(smem);
    const uint32_t sB = sbase + 16384;

    const int h  = blockIdx.z;
    const int bm = blockIdx.y, bn = blockIdx.x;
    const __nv_bfloat16* gA = g_lhs + ((size_t)h * MDIM + bm * 128) * KDIM;
    const __nv_bfloat16* gB = g_rhs + ((size_t)h * NDIM + bn * 128) * KDIM;
    const int tid = threadIdx.x;

#pragma unroll
    for (int i = 0; i < 4; i++) {
        int idx = i * 256 + tid;        // 0..1023 per operand
        int row = idx >> 3, j = idx & 7;
        int sw = j ^ (row & 7);
        uint32_t dstA = sbase + row * 128 + sw * 16;
        const char* srcA = reinterpret_cast<const char*>(gA + (size_t)row * KDIM) + j * 16;
        asm volatile("cp.async.cg.shared.global [%0], [%1], 16;\n" :: "r"(dstA), "l"(srcA));
        uint32_t dstB = sB + row * 128 + sw * 16;
        const char* srcB = reinterpret_cast<const char*>(gB + (size_t)row * KDIM) + j * 16;
        asm volatile("cp.async.cg.shared.global [%0], [%1], 16;\n" :: "r"(dstB), "l"(srcB));
    }
    asm volatile("cp.async.commit_group;\n" ::: "memory");
    asm volatile("cp.async.wait_group 0;\n" ::: "memory");
    __syncthreads();

    const int lane = tid & 31;
    const int wid  = tid >> 5;
    const int wm   = (wid & 1) * 64;
    const int wn   = (wid >> 1) * 32;
    const int g    = lane >> 2;
    const int t4   = lane & 3;

    float acc[4][4][4];
#pragma unroll
    for (int mt = 0; mt < 4; mt++)
#pragma unroll
        for (int nt = 0; nt < 4; nt++)
#pragma unroll
            for (int i = 0; i < 4; i++) acc[mt][nt][i] = 0.f;

    const int brow_base = wn + (lane & 7);
    const int bphase    = (lane >> 3) & 1;

#pragma unroll
    for (int ks = 0; ks < 4; ks++) {
        uint32_t a[4][4];
#pragma unroll
        for (int mt = 0; mt < 4; mt++) {
            int row = wm + mt * 16 + (lane & 15);
            int cu  = (ks * 2 + (lane >> 4)) ^ (row & 7);
            uint32_t addr = sbase + row * 128 + cu * 16;
            asm volatile("ldmatrix.sync.aligned.m8n8.x4.shared.b16 {%0,%1,%2,%3}, [%4];\n"
                         : "=r"(a[mt][0]), "=r"(a[mt][1]), "=r"(a[mt][2]), "=r"(a[mt][3])
                         : "r"(addr));
        }
        uint32_t b_cur0, b_cur1, b_nxt0, b_nxt1;
        {
            int row = brow_base;
            int cu  = (ks * 2 + bphase) ^ (row & 7);
            asm volatile("ldmatrix.sync.aligned.m8n8.x2.shared.b16 {%0,%1}, [%2];\n"
                         : "=r"(b_cur0), "=r"(b_cur1)
                         : "r"(sB + row * 128 + cu * 16));
        }
#pragma unroll
        for (int nt = 0; nt < 4; nt++) {
            if (nt < 3) {
                int row = brow_base + (nt + 1) * 8;
                int cu  = (ks * 2 + bphase) ^ (row & 7);
                asm volatile("ldmatrix.sync.aligned.m8n8.x2.shared.b16 {%0,%1}, [%2];\n"
                             : "=r"(b_nxt0), "=r"(b_nxt1)
                             : "r"(sB + row * 128 + cu * 16));
            }
#pragma unroll
            for (int mt = 0; mt < 4; mt++) {
                asm volatile(
                    "mma.sync.aligned.m16n8k16.row.col.f32.bf16.bf16.f32 "
                    "{%0,%1,%2,%3}, {%4,%5,%6,%7}, {%8,%9}, {%0,%1,%2,%3};\n"
                    : "+f"(acc[mt][nt][0]), "+f"(acc[mt][nt][1]),
                      "+f"(acc[mt][nt][2]), "+f"(acc[mt][nt][3])
                    : "r"(a[mt][0]), "r"(a[mt][1]), "r"(a[mt][2]), "r"(a[mt][3]),
                      "r"(b_cur0), "r"(b_cur1));
            }
            b_cur0 = b_nxt0;
            b_cur1 = b_nxt1;
        }
    }

    // Write-through stores: zero-reuse output, skip L2 dirty-allocation.
    float* gO = out + (size_t)h * MDIM * NDIM + (size_t)(bm * 128) * NDIM + bn * 128;
#pragma unroll
    for (int mt = 0; mt < 4; mt++) {
#pragma unroll
        for (int nt = 0; nt < 4; nt++) {
            int r0 = wm + mt * 16 + g;
            int c0 = wn + nt * 8 + t4 * 2;
            __stwt(reinterpret_cast<float2*>(&gO[(size_t)r0 * NDIM + c0]),
                   make_float2(acc[mt][nt][0], acc[mt][nt][1]));
            __stwt(reinterpret_cast<float2*>(&gO[(size_t)(r0 + 8) * NDIM + c0]),
                   make_float2(acc[mt][nt][2], acc[mt][nt][3]));
        }
    }
}

extern "C" void kernel_launch(void* const* d_in, const int* in_sizes, int n_in,
                              void* d_out, int out_size) {
    (void)in_sizes; (void)n_in; (void)out_size;
    const float* lhs = (const float*)d_in[0];  // [1,16,4096,64]
    const float* rhs = (const float*)d_in[1];  // [1,16,64,4096]
    float* out = (float*)d_out;                // [1,16,4096,4096]

    quant_all_kernel<<<QL_BLOCKS + QR_BLOCKS, 256>>>(lhs, rhs);

    dim3 grid(NDIM / 128, MDIM / 128, HEADS);
    bfp_gemm_kernel<<<grid, 256>>>(out);
}

// round 16
// speedup vs baseline: 1.0372x; 1.0372x over previous
#include <cuda_runtime.h>
#include <cuda_bf16.h>
#include <stdint.h>

#define HEADS 16
#define MDIM 4096
#define NDIM 4096
#define KDIM 64
#define QBLK 32

// Quantized (dequantized-to-bf16, exact) operands. rhs stored transposed: [h][n][k].
static __device__ __nv_bfloat16 g_lhs[(size_t)HEADS * MDIM * KDIM];
static __device__ __nv_bfloat16 g_rhs[(size_t)HEADS * NDIM * KDIM];

// ===========================================================================
// Quant phase (R3/R8-proven): fused lhs+rhs BFP quantization, bf16-exact.
// Two adjacent threads share one 32-block; block max via shfl_xor(1).
// All arithmetic exact in fp32 (power-of-two scaling); results have <=8
// significant bits -> exact in bf16 -> rel_err 0 vs reference.
// ===========================================================================
__device__ __forceinline__ void quant_half16(float v[16]) {
    float ma = 0.f;
#pragma unroll
    for (int i = 0; i < 16; i++) ma = fmaxf(ma, fabsf(v[i]));
    ma = fmaxf(ma, __shfl_xor_sync(0xFFFFFFFFu, ma, 1));  // full 32-block max
    if (ma > 0.f) {
        int e = ilogbf(fmaxf(ma, 1e-38f));       // floor(log2(.)) exactly
        float scale = exp2f((float)(7 - e));     // exact power of two
        float step  = exp2f((float)(e - 7));
#pragma unroll
        for (int i = 0; i < 16; i++) {
            float q = rintf(v[i] * scale);       // round-half-even
            q = fminf(fmaxf(q, -128.f), 127.f);
            v[i] = q * step;                     // exact
        }
    } else {
#pragma unroll
        for (int i = 0; i < 16; i++) v[i] = 0.f;
    }
}

__device__ __forceinline__ void pack_store16(__nv_bfloat16* dst, const float v[16]) {
    uint32_t pk[8];
#pragma unroll
    for (int j = 0; j < 8; j++) {
        __nv_bfloat162 h2 = __floats2bfloat162_rn(v[2 * j], v[2 * j + 1]);
        pk[j] = *reinterpret_cast<uint32_t*>(&h2);
    }
    uint4* d4 = reinterpret_cast<uint4*>(dst);
    d4[0] = make_uint4(pk[0], pk[1], pk[2], pk[3]);
    d4[1] = make_uint4(pk[4], pk[5], pk[6], pk[7]);
}

#define QL_BLOCKS 1024
#define QR_BLOCKS 1024

__global__ void __launch_bounds__(256) quant_all_kernel(
    const float* __restrict__ lhs, const float* __restrict__ rhs) {
    if (blockIdx.x < QL_BLOCKS) {
        // lhs [h][m][64]: thread owns 16 consecutive floats.
        size_t t = blockIdx.x * (size_t)blockDim.x + threadIdx.x;
        const float4* src = reinterpret_cast<const float4*>(lhs + t * 16);
        float v[16];
#pragma unroll
        for (int j = 0; j < 4; j++) {
            float4 f = __ldg(src + j);
            v[4 * j] = f.x; v[4 * j + 1] = f.y; v[4 * j + 2] = f.z; v[4 * j + 3] = f.w;
        }
        quant_half16(v);
        pack_store16(g_lhs + t * 16, v);
    } else {
        // rhs [h][k=64][n]: blocks along k (stride NDIM); transpose on write.
        int t    = (blockIdx.x - QL_BLOCKS) * blockDim.x + threadIdx.x;
        int half = t & 1;
        int pair = t >> 1;
        int c  = pair & (NDIM - 1);
        int kb = (pair >> 12) & 1;
        int h  = pair >> 13;
        const float* src = rhs + ((size_t)h * KDIM + kb * QBLK + half * 16) * NDIM + c;
        float v[16];
#pragma unroll
        for (int k = 0; k < 16; k++) v[k] = __ldg(src + (size_t)k * NDIM);
        quant_half16(v);
        pack_store16(g_rhs + (((size_t)h * NDIM + c) * KDIM + kb * QBLK + half * 16), v);
    }
}

// ===========================================================================
// GEMM (R8 = best measured, final): out[h][m][n] = sum_k A[m][k]*B[n][k].
// CTA tile 128x128, K=64 fully resident. 8 warps = 2(m) x 4(n), warp 64x32.
// cp.async staging into XOR-swizzled 128B rows (one L1 pass), bf16
// mma.m16n8k16 with fp32 accum, __stcs streaming epilogue, 2 CTAs/SM.
// Plateau: ~5.0 TB/s effective write stream == practical HBM write ceiling.
// ===========================================================================
__global__ void __launch_bounds__(256, 2) bfp_gemm_kernel(float* __restrict__ out) {
    __shared__ __align__(128) char smem[32768];   // A: 16KB, B: 16KB
    const uint32_t sbase = (uint32_t)__cvta_generic_to_shared(smem);
    const uint32_t sB = sbase + 16384;

    const int h  = blockIdx.z;
    const int bm = blockIdx.y, bn = blockIdx.x;
    const __nv_bfloat16* gA = g_lhs + ((size_t)h * MDIM + bm * 128) * KDIM;
    const __nv_bfloat16* gB = g_rhs + ((size_t)h * NDIM + bn * 128) * KDIM;
    const int tid = threadIdx.x;

    // Stage A + B (128 rows x 128B each) via cp.async, 16B units.
    // Swizzle: unit j -> j ^ (row & 7) -> conflict-free ldmatrix phases.
#pragma unroll
    for (int i = 0; i < 4; i++) {
        int idx = i * 256 + tid;        // 0..1023 per operand
        int row = idx >> 3, j = idx & 7;
        int sw = j ^ (row & 7);
        uint32_t dstA = sbase + row * 128 + sw * 16;
        const char* srcA = reinterpret_cast<const char*>(gA + (size_t)row * KDIM) + j * 16;
        asm volatile("cp.async.cg.shared.global [%0], [%1], 16;\n" :: "r"(dstA), "l"(srcA));
        uint32_t dstB = sB + row * 128 + sw * 16;
        const char* srcB = reinterpret_cast<const char*>(gB + (size_t)row * KDIM) + j * 16;
        asm volatile("cp.async.cg.shared.global [%0], [%1], 16;\n" :: "r"(dstB), "l"(srcB));
    }
    asm volatile("cp.async.commit_group;\n" ::: "memory");
    asm volatile("cp.async.wait_group 0;\n" ::: "memory");
    __syncthreads();

    const int lane = tid & 31;
    const int wid  = tid >> 5;
    const int wm   = (wid & 1) * 64;    // 2 m-warps, warp covers 64 rows
    const int wn   = (wid >> 1) * 32;   // 4 n-warps, warp covers 32 cols
    const int g    = lane >> 2;
    const int t4   = lane & 3;

    float acc[4][4][4];
#pragma unroll
    for (int mt = 0; mt < 4; mt++)
#pragma unroll
        for (int nt = 0; nt < 4; nt++)
#pragma unroll
            for (int i = 0; i < 4; i++) acc[mt][nt][i] = 0.f;

#pragma unroll
    for (int ks = 0; ks < 4; ks++) {
        uint32_t a[4][4];
#pragma unroll
        for (int mt = 0; mt < 4; mt++) {
            int row = wm + mt * 16 + (lane & 15);
            int cu  = (ks * 2 + (lane >> 4)) ^ (row & 7);
            uint32_t addr = sbase + row * 128 + cu * 16;
            asm volatile("ldmatrix.sync.aligned.m8n8.x4.shared.b16 {%0,%1,%2,%3}, [%4];\n"
                         : "=r"(a[mt][0]), "=r"(a[mt][1]), "=r"(a[mt][2]), "=r"(a[mt][3])
                         : "r"(addr));
        }
#pragma unroll
        for (int nt = 0; nt < 4; nt++) {
            int row = wn + nt * 8 + (lane & 7);
            int cu  = (ks * 2 + ((lane >> 3) & 1)) ^ (row & 7);
            uint32_t addr = sB + row * 128 + cu * 16;
            uint32_t b0, b1;
            asm volatile("ldmatrix.sync.aligned.m8n8.x2.shared.b16 {%0,%1}, [%2];\n"
                         : "=r"(b0), "=r"(b1) : "r"(addr));
#pragma unroll
            for (int mt = 0; mt < 4; mt++) {
                asm volatile(
                    "mma.sync.aligned.m16n8k16.row.col.f32.bf16.bf16.f32 "
                    "{%0,%1,%2,%3}, {%4,%5,%6,%7}, {%8,%9}, {%0,%1,%2,%3};\n"
                    : "+f"(acc[mt][nt][0]), "+f"(acc[mt][nt][1]),
                      "+f"(acc[mt][nt][2]), "+f"(acc[mt][nt][3])
                    : "r"(a[mt][0]), "r"(a[mt][1]), "r"(a[mt][2]), "r"(a[mt][3]),
                      "r"(b0), "r"(b1));
            }
        }
    }

    // Streaming stores: 32B-sector-aligned float2 per lane, evict-first.
    float* gO = out + (size_t)h * MDIM * NDIM + (size_t)(bm * 128) * NDIM + bn * 128;
#pragma unroll
    for (int mt = 0; mt < 4; mt++) {
#pragma unroll
        for (int nt = 0; nt < 4; nt++) {
            int r0 = wm + mt * 16 + g;
            int c0 = wn + nt * 8 + t4 * 2;
            __stcs(reinterpret_cast<float2*>(&gO[(size_t)r0 * NDIM + c0]),
                   make_float2(acc[mt][nt][0], acc[mt][nt][1]));
            __stcs(reinterpret_cast<float2*>(&gO[(size_t)(r0 + 8) * NDIM + c0]),
                   make_float2(acc[mt][nt][2], acc[mt][nt][3]));
        }
    }
}

extern "C" void kernel_launch(void* const* d_in, const int* in_sizes, int n_in,
                              void* d_out, int out_size) {
    (void)in_sizes; (void)n_in; (void)out_size;
    const float* lhs = (const float*)d_in[0];  // [1,16,4096,64]
    const float* rhs = (const float*)d_in[1];  // [1,16,64,4096]
    float* out = (float*)d_out;                // [1,16,4096,4096]

    quant_all_kernel<<<QL_BLOCKS + QR_BLOCKS, 256>>>(lhs, rhs);

    dim3 grid(NDIM / 128, MDIM / 128, HEADS);
    bfp_gemm_kernel<<<grid, 256>>>(out);
}